// round 2
// baseline (speedup 1.0000x reference)
#include <cuda_runtime.h>
#include <math.h>

// ---------------------------------------------------------------------------
// GAT 2-layer: N=50000 nodes, E=800000 edges (+N self loops), F=128.
// Layer1: heads=4, out_ch=32 (H*C=128).  Layer2: heads=1, out_ch=128.
// ---------------------------------------------------------------------------

#define NMAX   50048
#define ETMAX  (800000 + NMAX)

__device__ float g_h[(size_t)NMAX * 128];     // h1, then reused as h2
__device__ float g_agg[(size_t)NMAX * 128];   // layer1 aggregation result
__device__ float g_aS[NMAX * 4];
__device__ float g_aD[NMAX * 4];
__device__ float g_emax[NMAX * 4];
__device__ float g_denom[NMAX * 4];
__device__ float g_escr[(size_t)ETMAX * 4];   // per-edge scratch (e, then exp)
__device__ int   g_is64;

// ---------------------------------------------------------------------------
// helpers
// ---------------------------------------------------------------------------
__device__ __forceinline__ void atomicMaxFloat(float* addr, float val) {
    if (val >= 0.f)
        atomicMax((int*)addr, __float_as_int(val));
    else
        atomicMin((unsigned int*)addr, (unsigned int)__float_as_int(val));
}

__device__ __forceinline__ int loadIdx(const void* ei, long long pos) {
    if (g_is64) return (int)((const long long*)ei)[pos];
    return ((const int*)ei)[pos];
}

// ---------------------------------------------------------------------------
// dtype detection: int64 edge_index has zero high words
// ---------------------------------------------------------------------------
__global__ void detect_kernel(const int* ei) {
    int z = 0;
    for (int i = 0; i < 32; i++)
        if (ei[2 * i + 1] == 0) z++;
    g_is64 = (z >= 30) ? 1 : 0;
}

// ---------------------------------------------------------------------------
// fills
// ---------------------------------------------------------------------------
__global__ void fill_kernel(float* p, float v, int count) {
    int i = blockIdx.x * blockDim.x + threadIdx.x;
    if (i < count) p[i] = v;
}

__global__ void out_bias_init(float* out, const float* __restrict__ b, int count) {
    int i = blockIdx.x * blockDim.x + threadIdx.x;
    if (i < count) out[i] = b[i & 127];
}

// ---------------------------------------------------------------------------
// GEMM: C[M,128] = op(A)[M,128] @ W[128,128]
// op(A) = RELU_BIAS ? relu(A + bias) : A
// 128x128 tile per block, 256 threads, 8x8 per thread, BK=16.
// ---------------------------------------------------------------------------
template <bool RELU_BIAS>
__global__ void gemm128(const float* __restrict__ A, const float* __restrict__ W,
                        const float* __restrict__ bias, float* __restrict__ C, int M)
{
    __shared__ float Ast[16][132];   // transposed A chunk, padded
    __shared__ float Bs[16][128];

    int t  = threadIdx.x;            // 0..255
    int tx = t & 15, ty = t >> 4;
    int rowBase = blockIdx.x * 128;

    float acc[8][8];
#pragma unroll
    for (int i = 0; i < 8; i++)
#pragma unroll
        for (int j = 0; j < 8; j++) acc[i][j] = 0.f;

    for (int k0 = 0; k0 < 128; k0 += 16) {
        // load A chunk: 128 rows x 16 k -> 512 float4, 2 per thread
#pragma unroll
        for (int r = 0; r < 2; r++) {
            int i    = t + r * 256;
            int arow = i >> 2;
            int k4   = (i & 3) * 4;
            int grow = rowBase + arow;
            float4 v = make_float4(0.f, 0.f, 0.f, 0.f);
            if (grow < M)
                v = *(const float4*)(A + (size_t)grow * 128 + k0 + k4);
            if (RELU_BIAS) {
                const float* bb = bias + k0 + k4;
                v.x = fmaxf(v.x + bb[0], 0.f);
                v.y = fmaxf(v.y + bb[1], 0.f);
                v.z = fmaxf(v.z + bb[2], 0.f);
                v.w = fmaxf(v.w + bb[3], 0.f);
            }
            Ast[k4 + 0][arow] = v.x;
            Ast[k4 + 1][arow] = v.y;
            Ast[k4 + 2][arow] = v.z;
            Ast[k4 + 3][arow] = v.w;
        }
        // load W chunk rows k0..k0+15 x 128 cols
#pragma unroll
        for (int r = 0; r < 2; r++) {
            int i    = t + r * 256;
            int krow = i >> 5;
            int col  = (i & 31) * 4;
            *(float4*)(&Bs[krow][col]) =
                *(const float4*)(W + (size_t)(k0 + krow) * 128 + col);
        }
        __syncthreads();

#pragma unroll
        for (int kk = 0; kk < 16; kk++) {
            float4 a0 = *(float4*)(&Ast[kk][ty * 8]);
            float4 a1 = *(float4*)(&Ast[kk][ty * 8 + 4]);
            float4 b0 = *(float4*)(&Bs[kk][tx * 8]);
            float4 b1 = *(float4*)(&Bs[kk][tx * 8 + 4]);
            float av[8] = {a0.x, a0.y, a0.z, a0.w, a1.x, a1.y, a1.z, a1.w};
            float bv[8] = {b0.x, b0.y, b0.z, b0.w, b1.x, b1.y, b1.z, b1.w};
#pragma unroll
            for (int i = 0; i < 8; i++)
#pragma unroll
                for (int j = 0; j < 8; j++)
                    acc[i][j] += av[i] * bv[j];
        }
        __syncthreads();
    }

#pragma unroll
    for (int i = 0; i < 8; i++) {
        int grow = rowBase + ty * 8 + i;
        if (grow < M) {
            *(float4*)(C + (size_t)grow * 128 + tx * 8) =
                make_float4(acc[i][0], acc[i][1], acc[i][2], acc[i][3]);
            *(float4*)(C + (size_t)grow * 128 + tx * 8 + 4) =
                make_float4(acc[i][4], acc[i][5], acc[i][6], acc[i][7]);
        }
    }
}

// ---------------------------------------------------------------------------
// alpha_src / alpha_dst:  a[n][h] = sum_c h[n,h,c] * att[h,c]
// one warp per node; lane handles 4 channels
// ---------------------------------------------------------------------------
template <int H>
__global__ void alpha_kernel(const float* __restrict__ h,
                             const float* __restrict__ attS,
                             const float* __restrict__ attD,
                             float* __restrict__ aS, float* __restrict__ aD, int n)
{
    int w    = (int)((blockIdx.x * (size_t)blockDim.x + threadIdx.x) >> 5);
    int lane = threadIdx.x & 31;
    if (w >= n) return;
    float4 v = *(const float4*)(h + (size_t)w * 128 + lane * 4);
    float4 s = *(const float4*)(attS + lane * 4);
    float4 d = *(const float4*)(attD + lane * 4);
    float ps = v.x * s.x + v.y * s.y + v.z * s.z + v.w * s.w;
    float pd = v.x * d.x + v.y * d.y + v.z * d.z + v.w * d.w;
    const int LPH = 32 / H;   // lanes per head
#pragma unroll
    for (int o = LPH >> 1; o; o >>= 1) {
        ps += __shfl_xor_sync(0xffffffffu, ps, o);
        pd += __shfl_xor_sync(0xffffffffu, pd, o);
    }
    if ((lane & (LPH - 1)) == 0) {
        int hd = lane / LPH;
        aS[(size_t)w * H + hd] = ps;
        aD[(size_t)w * H + hd] = pd;
    }
}

// ---------------------------------------------------------------------------
// pass B: per-edge leaky(e) -> scratch, segment max via atomics
// ---------------------------------------------------------------------------
template <int H>
__global__ void edge_max_kernel(const void* __restrict__ ei, int E, int n,
                                const float* __restrict__ aS,
                                const float* __restrict__ aD,
                                float* __restrict__ escr, float* __restrict__ emax)
{
    int et = blockIdx.x * blockDim.x + threadIdx.x;
    int ET = E + n;
    if (et >= ET) return;
    int s, d;
    if (et < E) { s = loadIdx(ei, et); d = loadIdx(ei, (long long)E + et); }
    else        { s = d = et - E; }
#pragma unroll
    for (int h = 0; h < H; h++) {
        float ev = aS[(size_t)s * H + h] + aD[(size_t)d * H + h];
        ev = ev > 0.f ? ev : 0.2f * ev;
        escr[(size_t)et * H + h] = ev;
        atomicMaxFloat(&emax[(size_t)d * H + h], ev);
    }
}

// ---------------------------------------------------------------------------
// pass C: exp(e - emax[d]) -> scratch, segment sum of denominators
// ---------------------------------------------------------------------------
template <int H>
__global__ void edge_sum_kernel(const void* __restrict__ ei, int E, int n,
                                float* __restrict__ escr,
                                const float* __restrict__ emax,
                                float* __restrict__ denom)
{
    int et = blockIdx.x * blockDim.x + threadIdx.x;
    int ET = E + n;
    if (et >= ET) return;
    int d;
    if (et < E) d = loadIdx(ei, (long long)E + et);
    else        d = et - E;
#pragma unroll
    for (int h = 0; h < H; h++) {
        float ex = __expf(escr[(size_t)et * H + h] - emax[(size_t)d * H + h]);
        escr[(size_t)et * H + h] = ex;
        atomicAdd(&denom[(size_t)d * H + h], ex);
    }
}

// ---------------------------------------------------------------------------
// pass D: out[d] += (ex / denom[d]) * h[s]   -- one warp per edge
// ---------------------------------------------------------------------------
template <int H>
__global__ void edge_agg_kernel(const void* __restrict__ ei, int E, int n,
                                const float* __restrict__ escr,
                                const float* __restrict__ denom,
                                const float* __restrict__ hmat,
                                float* __restrict__ out)
{
    long long gt = blockIdx.x * (long long)blockDim.x + threadIdx.x;
    int gw   = (int)(gt >> 5);
    int lane = threadIdx.x & 31;
    int ET   = E + n;
    if (gw >= ET) return;
    int s, d;
    if (gw < E) { s = loadIdx(ei, gw); d = loadIdx(ei, (long long)E + gw); }
    else        { s = d = gw - E; }
    const int OC = 128 / H;
    int hd = (lane * 4) / OC;
    float ex  = escr[(size_t)gw * H + hd];
    float den = denom[(size_t)d * H + hd];
    float alpha = ex / fmaxf(den, 1e-16f);
    float4 v = *(const float4*)(hmat + (size_t)s * 128 + lane * 4);
    float* o = out + (size_t)d * 128 + lane * 4;
    atomicAdd(o + 0, alpha * v.x);
    atomicAdd(o + 1, alpha * v.y);
    atomicAdd(o + 2, alpha * v.z);
    atomicAdd(o + 3, alpha * v.w);
}

// ---------------------------------------------------------------------------
// host
// ---------------------------------------------------------------------------
extern "C" void kernel_launch(void* const* d_in, const int* in_sizes, int n_in,
                              void* d_out, int out_size)
{
    const float* x   = (const float*)d_in[0];
    const void*  ei  = d_in[1];
    const float* W1  = (const float*)d_in[2];
    const float* as1 = (const float*)d_in[3];
    const float* ad1 = (const float*)d_in[4];
    const float* b1  = (const float*)d_in[5];
    const float* W2  = (const float*)d_in[6];
    const float* as2 = (const float*)d_in[7];
    const float* ad2 = (const float*)d_in[8];
    const float* b2  = (const float*)d_in[9];
    float* out = (float*)d_out;

    int n  = in_sizes[0] / 128;
    int E  = in_sizes[1] / 2;
    int ET = E + n;

    float *h, *agg, *aS, *aD, *emax, *denom, *escr;
    cudaGetSymbolAddress((void**)&h,     g_h);
    cudaGetSymbolAddress((void**)&agg,   g_agg);
    cudaGetSymbolAddress((void**)&aS,    g_aS);
    cudaGetSymbolAddress((void**)&aD,    g_aD);
    cudaGetSymbolAddress((void**)&emax,  g_emax);
    cudaGetSymbolAddress((void**)&denom, g_denom);
    cudaGetSymbolAddress((void**)&escr,  g_escr);

    const int TB = 256;
    const float NEG_INF = -INFINITY;
    int gridGemm  = (n + 127) / 128;
    int gridEdge  = (ET + TB - 1) / TB;
    int gridEdgeW = (ET + 7) / 8;            // warp per edge, 8 warps/block
    int gridNodeW = (n + 7) / 8;             // warp per node

    detect_kernel<<<1, 1>>>((const int*)ei);

    // ----- layer 1 (H=4) -----
    fill_kernel<<<(n * 4 + TB - 1) / TB, TB>>>(emax, NEG_INF, n * 4);
    fill_kernel<<<(n * 4 + TB - 1) / TB, TB>>>(denom, 0.f, n * 4);
    fill_kernel<<<(n * 128 + TB - 1) / TB, TB>>>(agg, 0.f, n * 128);

    gemm128<false><<<gridGemm, TB>>>(x, W1, nullptr, h, n);
    alpha_kernel<4><<<gridNodeW, TB>>>(h, as1, ad1, aS, aD, n);
    edge_max_kernel<4><<<gridEdge, TB>>>(ei, E, n, aS, aD, escr, emax);
    edge_sum_kernel<4><<<gridEdge, TB>>>(ei, E, n, escr, emax, denom);
    edge_agg_kernel<4><<<gridEdgeW, TB>>>(ei, E, n, escr, denom, h, agg);

    // ----- layer 2 (H=1) -----
    fill_kernel<<<(n + TB - 1) / TB, TB>>>(emax, NEG_INF, n);
    fill_kernel<<<(n + TB - 1) / TB, TB>>>(denom, 0.f, n);
    out_bias_init<<<(n * 128 + TB - 1) / TB, TB>>>(out, b2, n * 128);

    gemm128<true><<<gridGemm, TB>>>(agg, W2, b1, h, n);   // relu(agg+b1) @ W2
    alpha_kernel<1><<<gridNodeW, TB>>>(h, as2, ad2, aS, aD, n);
    edge_max_kernel<1><<<gridEdge, TB>>>(ei, E, n, aS, aD, escr, emax);
    edge_sum_kernel<1><<<gridEdge, TB>>>(ei, E, n, escr, emax, denom);
    edge_agg_kernel<1><<<gridEdgeW, TB>>>(ei, E, n, escr, denom, h, out);
}

// round 3
// speedup vs baseline: 2.6487x; 2.6487x over previous
#include <cuda_runtime.h>
#include <math.h>

// ---------------------------------------------------------------------------
// GAT 2-layer: N=50000 nodes, E=800000 edges (+N self loops), F=128.
// Layer1: heads=4, out_ch=32.  Layer2: heads=1, out_ch=128.
// CSR-by-dst built once; per-node warp softmax+aggregation, no atomics on out.
// ---------------------------------------------------------------------------

#define NMAX   50048
#define ETMAX  (800000 + NMAX)

__device__ float g_h[(size_t)NMAX * 128];     // h1, then reused as h2
__device__ float g_agg[(size_t)NMAX * 128];   // layer1 aggregation result
__device__ float g_aS[NMAX * 4];
__device__ float g_aD[NMAX * 4];
__device__ int   g_deg[NMAX];
__device__ int   g_rowptr[NMAX + 1];
__device__ int   g_pos[NMAX];
__device__ int   g_colsrc[ETMAX];
__device__ int   g_is64;

// ---------------------------------------------------------------------------
__device__ __forceinline__ int loadIdx(const void* ei, long long pos) {
    if (g_is64) return (int)((const long long*)ei)[pos];
    return ((const int*)ei)[pos];
}

__global__ void detect_kernel(const int* ei) {
    int z = 0;
    for (int i = 0; i < 32; i++)
        if (ei[2 * i + 1] == 0) z++;
    g_is64 = (z >= 30) ? 1 : 0;
}

__global__ void zero_int(int* p, int count) {
    int i = blockIdx.x * blockDim.x + threadIdx.x;
    if (i < count) p[i] = 0;
}

// histogram of dst degrees (incl. self loops)
__global__ void hist_kernel(const void* __restrict__ ei, int E, int n, int* deg) {
    int et = blockIdx.x * blockDim.x + threadIdx.x;
    int ET = E + n;
    if (et >= ET) return;
    int d = (et < E) ? loadIdx(ei, (long long)E + et) : et - E;
    atomicAdd(&deg[d], 1);
}

// single-block exclusive scan over deg -> rowptr, pos
__global__ void scan_kernel(const int* __restrict__ deg, int* rowptr, int* pos, int n) {
    __shared__ int wsum[32];
    __shared__ int carry;
    int t = threadIdx.x, lane = t & 31, w = t >> 5;
    if (t == 0) { carry = 0; rowptr[0] = 0; }
    __syncthreads();
    for (int base = 0; base < n; base += 1024) {
        int i = base + t;
        int v = (i < n) ? deg[i] : 0;
        // warp inclusive scan
        int incl = v;
#pragma unroll
        for (int off = 1; off < 32; off <<= 1) {
            int x = __shfl_up_sync(0xffffffffu, incl, off);
            if (lane >= off) incl += x;
        }
        if (lane == 31) wsum[w] = incl;
        __syncthreads();
        if (w == 0) {
            int s = wsum[lane];
            int si = s;
#pragma unroll
            for (int off = 1; off < 32; off <<= 1) {
                int x = __shfl_up_sync(0xffffffffu, si, off);
                if (lane >= off) si += x;
            }
            wsum[lane] = si - s;   // exclusive warp offsets
        }
        __syncthreads();
        incl += wsum[w] + carry;
        if (i < n) { rowptr[i + 1] = incl; pos[i] = incl - v; }
        __syncthreads();
        if (t == 1023) carry = incl;
        __syncthreads();
    }
}

// scatter src indices into CSR slots
__global__ void scatter_kernel(const void* __restrict__ ei, int E, int n,
                               int* pos, int* colsrc) {
    int et = blockIdx.x * blockDim.x + threadIdx.x;
    int ET = E + n;
    if (et >= ET) return;
    int s, d;
    if (et < E) { s = loadIdx(ei, et); d = loadIdx(ei, (long long)E + et); }
    else        { s = d = et - E; }
    int p = atomicAdd(&pos[d], 1);
    colsrc[p] = s;
}

// ---------------------------------------------------------------------------
// GEMM: C[M,128] = op(A)[M,128] @ W[128,128]
// ---------------------------------------------------------------------------
template <bool RELU_BIAS>
__global__ void gemm128(const float* __restrict__ A, const float* __restrict__ W,
                        const float* __restrict__ bias, float* __restrict__ C, int M)
{
    __shared__ float Ast[16][132];
    __shared__ float Bs[16][128];

    int t  = threadIdx.x;
    int tx = t & 15, ty = t >> 4;
    int rowBase = blockIdx.x * 128;

    float acc[8][8];
#pragma unroll
    for (int i = 0; i < 8; i++)
#pragma unroll
        for (int j = 0; j < 8; j++) acc[i][j] = 0.f;

    for (int k0 = 0; k0 < 128; k0 += 16) {
#pragma unroll
        for (int r = 0; r < 2; r++) {
            int i    = t + r * 256;
            int arow = i >> 2;
            int k4   = (i & 3) * 4;
            int grow = rowBase + arow;
            float4 v = make_float4(0.f, 0.f, 0.f, 0.f);
            if (grow < M)
                v = *(const float4*)(A + (size_t)grow * 128 + k0 + k4);
            if (RELU_BIAS) {
                const float* bb = bias + k0 + k4;
                v.x = fmaxf(v.x + bb[0], 0.f);
                v.y = fmaxf(v.y + bb[1], 0.f);
                v.z = fmaxf(v.z + bb[2], 0.f);
                v.w = fmaxf(v.w + bb[3], 0.f);
            }
            Ast[k4 + 0][arow] = v.x;
            Ast[k4 + 1][arow] = v.y;
            Ast[k4 + 2][arow] = v.z;
            Ast[k4 + 3][arow] = v.w;
        }
#pragma unroll
        for (int r = 0; r < 2; r++) {
            int i    = t + r * 256;
            int krow = i >> 5;
            int col  = (i & 31) * 4;
            *(float4*)(&Bs[krow][col]) =
                *(const float4*)(W + (size_t)(k0 + krow) * 128 + col);
        }
        __syncthreads();

#pragma unroll
        for (int kk = 0; kk < 16; kk++) {
            float4 a0 = *(float4*)(&Ast[kk][ty * 8]);
            float4 a1 = *(float4*)(&Ast[kk][ty * 8 + 4]);
            float4 b0 = *(float4*)(&Bs[kk][tx * 8]);
            float4 b1 = *(float4*)(&Bs[kk][tx * 8 + 4]);
            float av[8] = {a0.x, a0.y, a0.z, a0.w, a1.x, a1.y, a1.z, a1.w};
            float bv[8] = {b0.x, b0.y, b0.z, b0.w, b1.x, b1.y, b1.z, b1.w};
#pragma unroll
            for (int i = 0; i < 8; i++)
#pragma unroll
                for (int j = 0; j < 8; j++)
                    acc[i][j] += av[i] * bv[j];
        }
        __syncthreads();
    }

#pragma unroll
    for (int i = 0; i < 8; i++) {
        int grow = rowBase + ty * 8 + i;
        if (grow < M) {
            *(float4*)(C + (size_t)grow * 128 + tx * 8) =
                make_float4(acc[i][0], acc[i][1], acc[i][2], acc[i][3]);
            *(float4*)(C + (size_t)grow * 128 + tx * 8 + 4) =
                make_float4(acc[i][4], acc[i][5], acc[i][6], acc[i][7]);
        }
    }
}

// ---------------------------------------------------------------------------
// alpha_src / alpha_dst
// ---------------------------------------------------------------------------
template <int H>
__global__ void alpha_kernel(const float* __restrict__ h,
                             const float* __restrict__ attS,
                             const float* __restrict__ attD,
                             float* __restrict__ aS, float* __restrict__ aD, int n)
{
    int w    = (int)((blockIdx.x * (size_t)blockDim.x + threadIdx.x) >> 5);
    int lane = threadIdx.x & 31;
    if (w >= n) return;
    float4 v = *(const float4*)(h + (size_t)w * 128 + lane * 4);
    float4 s = *(const float4*)(attS + lane * 4);
    float4 d = *(const float4*)(attD + lane * 4);
    float ps = v.x * s.x + v.y * s.y + v.z * s.z + v.w * s.w;
    float pd = v.x * d.x + v.y * d.y + v.z * d.z + v.w * d.w;
    const int LPH = 32 / H;
#pragma unroll
    for (int o = LPH >> 1; o; o >>= 1) {
        ps += __shfl_xor_sync(0xffffffffu, ps, o);
        pd += __shfl_xor_sync(0xffffffffu, pd, o);
    }
    if ((lane & (LPH - 1)) == 0) {
        int hd = lane / LPH;
        aS[(size_t)w * H + hd] = ps;
        aD[(size_t)w * H + hd] = pd;
    }
}

// ---------------------------------------------------------------------------
// warp-per-node softmax + aggregation (no atomics)
// ---------------------------------------------------------------------------
template <int H, bool ADD_BIAS>
__global__ void node_agg_kernel(const int* __restrict__ rowptr,
                                const int* __restrict__ colsrc,
                                const float* __restrict__ aS,
                                const float* __restrict__ aD,
                                const float* __restrict__ hmat,
                                const float* __restrict__ bias,
                                float* __restrict__ out, int n)
{
    int d    = (int)((blockIdx.x * (size_t)blockDim.x + threadIdx.x) >> 5);
    int lane = threadIdx.x & 31;
    if (d >= n) return;
    int beg = rowptr[d], end = rowptr[d + 1];

    float aDd[H];
#pragma unroll
    for (int h = 0; h < H; h++) aDd[h] = aD[(size_t)d * H + h];

    // pass 1: per-head max
    float mx[H];
#pragma unroll
    for (int h = 0; h < H; h++) mx[h] = -INFINITY;
    for (int i = beg + lane; i < end; i += 32) {
        int s = colsrc[i];
#pragma unroll
        for (int h = 0; h < H; h++) {
            float e = aS[(size_t)s * H + h] + aDd[h];
            e = e > 0.f ? e : 0.2f * e;
            mx[h] = fmaxf(mx[h], e);
        }
    }
#pragma unroll
    for (int o = 16; o; o >>= 1)
#pragma unroll
        for (int h = 0; h < H; h++)
            mx[h] = fmaxf(mx[h], __shfl_xor_sync(0xffffffffu, mx[h], o));

    // pass 2: per-head denom
    float sm[H];
#pragma unroll
    for (int h = 0; h < H; h++) sm[h] = 0.f;
    for (int i = beg + lane; i < end; i += 32) {
        int s = colsrc[i];
#pragma unroll
        for (int h = 0; h < H; h++) {
            float e = aS[(size_t)s * H + h] + aDd[h];
            e = e > 0.f ? e : 0.2f * e;
            sm[h] += __expf(e - mx[h]);
        }
    }
#pragma unroll
    for (int o = 16; o; o >>= 1)
#pragma unroll
        for (int h = 0; h < H; h++)
            sm[h] += __shfl_xor_sync(0xffffffffu, sm[h], o);

    // pass 3: weighted aggregation; lane owns channels lane*4..lane*4+3
    const int OC = 128 / H;
    int hd = (lane * 4) / OC;
    float mxh  = mx[hd];
    float aDh  = aDd[hd];
    float inv  = 1.f / fmaxf(sm[hd], 1e-16f);
    float4 acc = make_float4(0.f, 0.f, 0.f, 0.f);
    for (int i = beg; i < end; i++) {
        int s = colsrc[i];                         // broadcast
        float e = aS[(size_t)s * H + hd] + aDh;
        e = e > 0.f ? e : 0.2f * e;
        float wgt = __expf(e - mxh) * inv;
        float4 v = *(const float4*)(hmat + (size_t)s * 128 + lane * 4);
        acc.x += wgt * v.x;
        acc.y += wgt * v.y;
        acc.z += wgt * v.z;
        acc.w += wgt * v.w;
    }
    if (ADD_BIAS) {
        float4 b = *(const float4*)(bias + lane * 4);
        acc.x += b.x; acc.y += b.y; acc.z += b.z; acc.w += b.w;
    }
    *(float4*)(out + (size_t)d * 128 + lane * 4) = acc;
}

// ---------------------------------------------------------------------------
// host
// ---------------------------------------------------------------------------
extern "C" void kernel_launch(void* const* d_in, const int* in_sizes, int n_in,
                              void* d_out, int out_size)
{
    const float* x   = (const float*)d_in[0];
    const void*  ei  = d_in[1];
    const float* W1  = (const float*)d_in[2];
    const float* as1 = (const float*)d_in[3];
    const float* ad1 = (const float*)d_in[4];
    const float* b1  = (const float*)d_in[5];
    const float* W2  = (const float*)d_in[6];
    const float* as2 = (const float*)d_in[7];
    const float* ad2 = (const float*)d_in[8];
    const float* b2  = (const float*)d_in[9];
    float* out = (float*)d_out;

    int n  = in_sizes[0] / 128;
    int E  = in_sizes[1] / 2;
    int ET = E + n;

    float *h, *agg, *aS, *aD;
    int *deg, *rowptr, *pos, *colsrc;
    cudaGetSymbolAddress((void**)&h,      g_h);
    cudaGetSymbolAddress((void**)&agg,    g_agg);
    cudaGetSymbolAddress((void**)&aS,     g_aS);
    cudaGetSymbolAddress((void**)&aD,     g_aD);
    cudaGetSymbolAddress((void**)&deg,    g_deg);
    cudaGetSymbolAddress((void**)&rowptr, g_rowptr);
    cudaGetSymbolAddress((void**)&pos,    g_pos);
    cudaGetSymbolAddress((void**)&colsrc, g_colsrc);

    const int TB = 256;
    int gridGemm  = (n + 127) / 128;
    int gridEdge  = (ET + TB - 1) / TB;
    int gridNodeW = (n + 7) / 8;             // warp per node, 8 warps/block

    // ----- CSR build (once, shared by both layers) -----
    detect_kernel<<<1, 1>>>((const int*)ei);
    zero_int<<<(n + TB - 1) / TB, TB>>>(deg, n);
    hist_kernel<<<gridEdge, TB>>>(ei, E, n, deg);
    scan_kernel<<<1, 1024>>>(deg, rowptr, pos, n);
    scatter_kernel<<<gridEdge, TB>>>(ei, E, n, pos, colsrc);

    // ----- layer 1 (H=4) -----
    gemm128<false><<<gridGemm, TB>>>(x, W1, nullptr, h, n);
    alpha_kernel<4><<<gridNodeW, TB>>>(h, as1, ad1, aS, aD, n);
    node_agg_kernel<4, false><<<gridNodeW, TB>>>(rowptr, colsrc, aS, aD, h,
                                                 nullptr, agg, n);

    // ----- layer 2 (H=1) -----
    gemm128<true><<<gridGemm, TB>>>(agg, W2, b1, h, n);   // relu(agg+b1) @ W2
    alpha_kernel<1><<<gridNodeW, TB>>>(h, as2, ad2, aS, aD, n);
    node_agg_kernel<1, true><<<gridNodeW, TB>>>(rowptr, colsrc, aS, aD, h,
                                                b2, out, n);
}

// round 4
// speedup vs baseline: 2.8376x; 1.0713x over previous
#include <cuda_runtime.h>
#include <math.h>

// ---------------------------------------------------------------------------
// GAT 2-layer: N=50000 nodes, E=800000 edges (+N self loops), F=128.
// Layer1: heads=4, out_ch=32.  Layer2: heads=1, out_ch=128.
// CSR-by-dst built once; per-node warp online-softmax+aggregation, no atomics.
// ---------------------------------------------------------------------------

#define NMAX   50048
#define ETMAX  (800000 + NMAX)
#define NEG_BIG (-1e30f)

__device__ float g_h[(size_t)NMAX * 128];     // h1, then reused as h2
__device__ float g_agg[(size_t)NMAX * 128];   // layer1 aggregation result
__device__ float g_aS[NMAX * 4];
__device__ float g_aD[NMAX * 4];
__device__ int   g_deg[NMAX];
__device__ int   g_rowptr[NMAX + 1];
__device__ int   g_pos[NMAX];
__device__ int   g_colsrc[ETMAX];
__device__ int   g_bsum[64];
__device__ int   g_is64;

// ---------------------------------------------------------------------------
__device__ __forceinline__ int loadIdx(const void* ei, long long pos) {
    if (g_is64) return (int)((const long long*)ei)[pos];
    return ((const int*)ei)[pos];
}

__global__ void detect_kernel(const int* ei) {
    int z = 0;
    for (int i = 0; i < 32; i++)
        if (ei[2 * i + 1] == 0) z++;
    g_is64 = (z >= 30) ? 1 : 0;
}

__global__ void zero_int(int* p, int count) {
    int i = blockIdx.x * blockDim.x + threadIdx.x;
    if (i < count) p[i] = 0;
}

// histogram of dst degrees (incl. self loops)
__global__ void hist_kernel(const void* __restrict__ ei, int E, int n, int* deg) {
    int et = blockIdx.x * blockDim.x + threadIdx.x;
    int ET = E + n;
    if (et >= ET) return;
    int d = (et < E) ? loadIdx(ei, (long long)E + et) : et - E;
    atomicAdd(&deg[d], 1);
}

// ---- 3-phase scan: block sums -> scan sums -> block rescan + offset -------
__global__ void block_sum_kernel(const int* __restrict__ deg, int* bsum, int n) {
    __shared__ int wsum[8];
    int t = threadIdx.x, lane = t & 31, w = t >> 5;
    int base = blockIdx.x * 1024 + t * 4;
    int v = 0;
#pragma unroll
    for (int i = 0; i < 4; i++)
        if (base + i < n) v += deg[base + i];
#pragma unroll
    for (int o = 16; o; o >>= 1) v += __shfl_xor_sync(0xffffffffu, v, o);
    if (lane == 0) wsum[w] = v;
    __syncthreads();
    if (t == 0) {
        int s = 0;
#pragma unroll
        for (int i = 0; i < 8; i++) s += wsum[i];
        bsum[blockIdx.x] = s;
    }
}

__global__ void scan_bsum_kernel(int* bsum, int nb) {
    int acc = 0;
    for (int i = 0; i < nb; i++) { int v = bsum[i]; bsum[i] = acc; acc += v; }
}

__global__ void scan_final_kernel(const int* __restrict__ deg,
                                  const int* __restrict__ bsum,
                                  int* rowptr, int* pos, int n) {
    __shared__ int wsum[8];
    int t = threadIdx.x, lane = t & 31, w = t >> 5;
    int base = blockIdx.x * 1024 + t * 4;
    int v[4], p[4];
    int run = 0;
#pragma unroll
    for (int i = 0; i < 4; i++) {
        v[i] = (base + i < n) ? deg[base + i] : 0;
        run += v[i];
        p[i] = run;                      // inclusive local prefix
    }
    int incl = run;
#pragma unroll
    for (int o = 1; o < 32; o <<= 1) {
        int x = __shfl_up_sync(0xffffffffu, incl, o);
        if (lane >= o) incl += x;
    }
    int wexcl = incl - run;
    if (lane == 31) wsum[w] = incl;
    __syncthreads();
    if (t == 0) {
        int a = 0;
#pragma unroll
        for (int i = 0; i < 8; i++) { int x = wsum[i]; wsum[i] = a; a += x; }
    }
    __syncthreads();
    int off = bsum[blockIdx.x] + wsum[w] + wexcl;
#pragma unroll
    for (int i = 0; i < 4; i++) {
        int idx = base + i;
        if (idx < n) {
            rowptr[idx + 1] = off + p[i];
            pos[idx]        = off + p[i] - v[i];
        }
    }
    if (blockIdx.x == 0 && t == 0) rowptr[0] = 0;
}

// scatter src indices into CSR slots
__global__ void scatter_kernel(const void* __restrict__ ei, int E, int n,
                               int* pos, int* colsrc) {
    int et = blockIdx.x * blockDim.x + threadIdx.x;
    int ET = E + n;
    if (et >= ET) return;
    int s, d;
    if (et < E) { s = loadIdx(ei, et); d = loadIdx(ei, (long long)E + et); }
    else        { s = d = et - E; }
    int p = atomicAdd(&pos[d], 1);
    colsrc[p] = s;
}

// ---------------------------------------------------------------------------
// GEMM: C[M,128] = op(A)[M,128] @ W[128,128]
// ---------------------------------------------------------------------------
template <bool RELU_BIAS>
__global__ void gemm128(const float* __restrict__ A, const float* __restrict__ W,
                        const float* __restrict__ bias, float* __restrict__ C, int M)
{
    __shared__ float Ast[16][132];
    __shared__ float Bs[16][128];

    int t  = threadIdx.x;
    int tx = t & 15, ty = t >> 4;
    int rowBase = blockIdx.x * 128;

    float acc[8][8];
#pragma unroll
    for (int i = 0; i < 8; i++)
#pragma unroll
        for (int j = 0; j < 8; j++) acc[i][j] = 0.f;

    for (int k0 = 0; k0 < 128; k0 += 16) {
#pragma unroll
        for (int r = 0; r < 2; r++) {
            int i    = t + r * 256;
            int arow = i >> 2;
            int k4   = (i & 3) * 4;
            int grow = rowBase + arow;
            float4 v = make_float4(0.f, 0.f, 0.f, 0.f);
            if (grow < M)
                v = *(const float4*)(A + (size_t)grow * 128 + k0 + k4);
            if (RELU_BIAS) {
                const float* bb = bias + k0 + k4;
                v.x = fmaxf(v.x + bb[0], 0.f);
                v.y = fmaxf(v.y + bb[1], 0.f);
                v.z = fmaxf(v.z + bb[2], 0.f);
                v.w = fmaxf(v.w + bb[3], 0.f);
            }
            Ast[k4 + 0][arow] = v.x;
            Ast[k4 + 1][arow] = v.y;
            Ast[k4 + 2][arow] = v.z;
            Ast[k4 + 3][arow] = v.w;
        }
#pragma unroll
        for (int r = 0; r < 2; r++) {
            int i    = t + r * 256;
            int krow = i >> 5;
            int col  = (i & 31) * 4;
            *(float4*)(&Bs[krow][col]) =
                *(const float4*)(W + (size_t)(k0 + krow) * 128 + col);
        }
        __syncthreads();

#pragma unroll
        for (int kk = 0; kk < 16; kk++) {
            float4 a0 = *(float4*)(&Ast[kk][ty * 8]);
            float4 a1 = *(float4*)(&Ast[kk][ty * 8 + 4]);
            float4 b0 = *(float4*)(&Bs[kk][tx * 8]);
            float4 b1 = *(float4*)(&Bs[kk][tx * 8 + 4]);
            float av[8] = {a0.x, a0.y, a0.z, a0.w, a1.x, a1.y, a1.z, a1.w};
            float bv[8] = {b0.x, b0.y, b0.z, b0.w, b1.x, b1.y, b1.z, b1.w};
#pragma unroll
            for (int i = 0; i < 8; i++)
#pragma unroll
                for (int j = 0; j < 8; j++)
                    acc[i][j] += av[i] * bv[j];
        }
        __syncthreads();
    }

#pragma unroll
    for (int i = 0; i < 8; i++) {
        int grow = rowBase + ty * 8 + i;
        if (grow < M) {
            *(float4*)(C + (size_t)grow * 128 + tx * 8) =
                make_float4(acc[i][0], acc[i][1], acc[i][2], acc[i][3]);
            *(float4*)(C + (size_t)grow * 128 + tx * 8 + 4) =
                make_float4(acc[i][4], acc[i][5], acc[i][6], acc[i][7]);
        }
    }
}

// ---------------------------------------------------------------------------
// alpha_src / alpha_dst
// ---------------------------------------------------------------------------
template <int H>
__global__ void alpha_kernel(const float* __restrict__ h,
                             const float* __restrict__ attS,
                             const float* __restrict__ attD,
                             float* __restrict__ aS, float* __restrict__ aD, int n)
{
    int w    = (int)((blockIdx.x * (size_t)blockDim.x + threadIdx.x) >> 5);
    int lane = threadIdx.x & 31;
    if (w >= n) return;
    float4 v = *(const float4*)(h + (size_t)w * 128 + lane * 4);
    float4 s = *(const float4*)(attS + lane * 4);
    float4 d = *(const float4*)(attD + lane * 4);
    float ps = v.x * s.x + v.y * s.y + v.z * s.z + v.w * s.w;
    float pd = v.x * d.x + v.y * d.y + v.z * d.z + v.w * d.w;
    const int LPH = 32 / H;
#pragma unroll
    for (int o = LPH >> 1; o; o >>= 1) {
        ps += __shfl_xor_sync(0xffffffffu, ps, o);
        pd += __shfl_xor_sync(0xffffffffu, pd, o);
    }
    if ((lane & (LPH - 1)) == 0) {
        int hd = lane / LPH;
        aS[(size_t)w * H + hd] = ps;
        aD[(size_t)w * H + hd] = pd;
    }
}

// ---------------------------------------------------------------------------
// warp-per-node online softmax + aggregation (no atomics)
// ---------------------------------------------------------------------------
template <int H, bool ADD_BIAS>
__global__ void node_agg_kernel(const int* __restrict__ rowptr,
                                const int* __restrict__ colsrc,
                                const float* __restrict__ aS,
                                const float* __restrict__ aD,
                                const float* __restrict__ hmat,
                                const float* __restrict__ bias,
                                float* __restrict__ out, int n)
{
    int d    = (int)((blockIdx.x * (size_t)blockDim.x + threadIdx.x) >> 5);
    int lane = threadIdx.x & 31;
    if (d >= n) return;
    int beg = rowptr[d], end = rowptr[d + 1];

    float aDd[H];
#pragma unroll
    for (int h = 0; h < H; h++) aDd[h] = aD[(size_t)d * H + h];

    // single online-softmax stats pass (running max m, running sum s)
    float m[H], s[H];
#pragma unroll
    for (int h = 0; h < H; h++) { m[h] = NEG_BIG; s[h] = 0.f; }
    for (int i = beg + lane; i < end; i += 32) {
        int sidx = colsrc[i];
#pragma unroll
        for (int h = 0; h < H; h++) {
            float e = aS[(size_t)sidx * H + h] + aDd[h];
            e = e > 0.f ? e : 0.2f * e;
            float mn = fmaxf(m[h], e);
            s[h] = s[h] * __expf(m[h] - mn) + __expf(e - mn);
            m[h] = mn;
        }
    }
    // warp combine
#pragma unroll
    for (int o = 16; o; o >>= 1) {
#pragma unroll
        for (int h = 0; h < H; h++) {
            float mo = __shfl_xor_sync(0xffffffffu, m[h], o);
            float so = __shfl_xor_sync(0xffffffffu, s[h], o);
            float mn = fmaxf(m[h], mo);
            s[h] = s[h] * __expf(m[h] - mn) + so * __expf(mo - mn);
            m[h] = mn;
        }
    }

    // aggregation pass; lane owns channels lane*4..lane*4+3
    const int OC = 128 / H;
    int hd = (lane * 4) / OC;
    float mxh = m[hd];
    float aDh = aDd[hd];
    float inv = 1.f / fmaxf(s[hd], 1e-16f);
    float4 acc = make_float4(0.f, 0.f, 0.f, 0.f);
    for (int base = beg; base < end; base += 32) {
        int cnt = min(32, end - base);
        int idx = base + lane;
        int sv  = (idx < end) ? colsrc[idx] : 0;
#pragma unroll 4
        for (int j = 0; j < cnt; j++) {
            int sidx = __shfl_sync(0xffffffffu, sv, j);
            float e = aS[(size_t)sidx * H + hd] + aDh;
            e = e > 0.f ? e : 0.2f * e;
            float wgt = __expf(e - mxh) * inv;
            float4 v = *(const float4*)(hmat + (size_t)sidx * 128 + lane * 4);
            acc.x += wgt * v.x;
            acc.y += wgt * v.y;
            acc.z += wgt * v.z;
            acc.w += wgt * v.w;
        }
    }
    if (ADD_BIAS) {
        float4 b = *(const float4*)(bias + lane * 4);
        acc.x += b.x; acc.y += b.y; acc.z += b.z; acc.w += b.w;
    }
    *(float4*)(out + (size_t)d * 128 + lane * 4) = acc;
}

// ---------------------------------------------------------------------------
// host
// ---------------------------------------------------------------------------
extern "C" void kernel_launch(void* const* d_in, const int* in_sizes, int n_in,
                              void* d_out, int out_size)
{
    const float* x   = (const float*)d_in[0];
    const void*  ei  = d_in[1];
    const float* W1  = (const float*)d_in[2];
    const float* as1 = (const float*)d_in[3];
    const float* ad1 = (const float*)d_in[4];
    const float* b1  = (const float*)d_in[5];
    const float* W2  = (const float*)d_in[6];
    const float* as2 = (const float*)d_in[7];
    const float* ad2 = (const float*)d_in[8];
    const float* b2  = (const float*)d_in[9];
    float* out = (float*)d_out;

    int n  = in_sizes[0] / 128;
    int E  = in_sizes[1] / 2;
    int ET = E + n;

    float *h, *agg, *aS, *aD;
    int *deg, *rowptr, *pos, *colsrc, *bsum;
    cudaGetSymbolAddress((void**)&h,      g_h);
    cudaGetSymbolAddress((void**)&agg,    g_agg);
    cudaGetSymbolAddress((void**)&aS,     g_aS);
    cudaGetSymbolAddress((void**)&aD,     g_aD);
    cudaGetSymbolAddress((void**)&deg,    g_deg);
    cudaGetSymbolAddress((void**)&rowptr, g_rowptr);
    cudaGetSymbolAddress((void**)&pos,    g_pos);
    cudaGetSymbolAddress((void**)&colsrc, g_colsrc);
    cudaGetSymbolAddress((void**)&bsum,   g_bsum);

    const int TB = 256;
    int gridGemm  = (n + 127) / 128;
    int gridEdge  = (ET + TB - 1) / TB;
    int gridNodeW = (n + 7) / 8;             // warp per node, 8 warps/block
    int nScanBlk  = (n + 1023) / 1024;

    // ----- CSR build (once, shared by both layers) -----
    detect_kernel<<<1, 1>>>((const int*)ei);
    zero_int<<<(n + TB - 1) / TB, TB>>>(deg, n);
    hist_kernel<<<gridEdge, TB>>>(ei, E, n, deg);
    block_sum_kernel<<<nScanBlk, 256>>>(deg, bsum, n);
    scan_bsum_kernel<<<1, 1>>>(bsum, nScanBlk);
    scan_final_kernel<<<nScanBlk, 256>>>(deg, bsum, rowptr, pos, n);
    scatter_kernel<<<gridEdge, TB>>>(ei, E, n, pos, colsrc);

    // ----- layer 1 (H=4) -----
    gemm128<false><<<gridGemm, TB>>>(x, W1, nullptr, h, n);
    alpha_kernel<4><<<gridNodeW, TB>>>(h, as1, ad1, aS, aD, n);
    node_agg_kernel<4, false><<<gridNodeW, TB>>>(rowptr, colsrc, aS, aD, h,
                                                 nullptr, agg, n);

    // ----- layer 2 (H=1) -----
    gemm128<true><<<gridGemm, TB>>>(agg, W2, b1, h, n);   // relu(agg+b1) @ W2
    alpha_kernel<1><<<gridNodeW, TB>>>(h, as2, ad2, aS, aD, n);
    node_agg_kernel<1, true><<<gridNodeW, TB>>>(rowptr, colsrc, aS, aD, h,
                                                b2, out, n);
}

// round 5
// speedup vs baseline: 3.6881x; 1.2997x over previous
#include <cuda_runtime.h>
#include <math.h>

// ---------------------------------------------------------------------------
// GAT 2-layer: N=50000 nodes, E=800000 edges (+N self loops), F=128.
// Layer1: heads=4, out_ch=32.  Layer2: heads=1, out_ch=128.
// CSR-by-dst built once; warp online-softmax+aggregation; tf32 tensor GEMM.
// ---------------------------------------------------------------------------

#define NMAX   50048
#define ETMAX  (800000 + NMAX)
#define NEG_BIG (-1e30f)

__device__ float g_h[(size_t)NMAX * 128];
__device__ float g_agg[(size_t)NMAX * 128];
__device__ float g_aS[NMAX * 4];
__device__ float g_aD[NMAX * 4];
__device__ int   g_deg[NMAX];
__device__ int   g_rowptr[NMAX + 1];
__device__ int   g_pos[NMAX];
__device__ int   g_colsrc[ETMAX];
__device__ int   g_bsum[64];
__device__ int   g_is64;

// ---------------------------------------------------------------------------
__device__ __forceinline__ int loadIdx(const void* ei, long long pos) {
    if (g_is64) return (int)((const long long*)ei)[pos];
    return ((const int*)ei)[pos];
}

__global__ void detect_kernel(const int* ei) {
    int z = 0;
    for (int i = 0; i < 32; i++)
        if (ei[2 * i + 1] == 0) z++;
    g_is64 = (z >= 30) ? 1 : 0;
}

__global__ void zero_int(int* p, int count) {
    int i = blockIdx.x * blockDim.x + threadIdx.x;
    if (i < count) p[i] = 0;
}

__global__ void hist_kernel(const void* __restrict__ ei, int E, int n, int* deg) {
    int et = blockIdx.x * blockDim.x + threadIdx.x;
    int ET = E + n;
    if (et >= ET) return;
    int d = (et < E) ? loadIdx(ei, (long long)E + et) : et - E;
    atomicAdd(&deg[d], 1);
}

// ---- 3-phase scan --------------------------------------------------------
__global__ void block_sum_kernel(const int* __restrict__ deg, int* bsum, int n) {
    __shared__ int wsum[8];
    int t = threadIdx.x, lane = t & 31, w = t >> 5;
    int base = blockIdx.x * 1024 + t * 4;
    int v = 0;
#pragma unroll
    for (int i = 0; i < 4; i++)
        if (base + i < n) v += deg[base + i];
#pragma unroll
    for (int o = 16; o; o >>= 1) v += __shfl_xor_sync(0xffffffffu, v, o);
    if (lane == 0) wsum[w] = v;
    __syncthreads();
    if (t == 0) {
        int s = 0;
#pragma unroll
        for (int i = 0; i < 8; i++) s += wsum[i];
        bsum[blockIdx.x] = s;
    }
}

__global__ void scan_bsum_kernel(int* bsum, int nb) {
    int acc = 0;
    for (int i = 0; i < nb; i++) { int v = bsum[i]; bsum[i] = acc; acc += v; }
}

__global__ void scan_final_kernel(const int* __restrict__ deg,
                                  const int* __restrict__ bsum,
                                  int* rowptr, int* pos, int n) {
    __shared__ int wsum[8];
    int t = threadIdx.x, lane = t & 31, w = t >> 5;
    int base = blockIdx.x * 1024 + t * 4;
    int v[4], p[4];
    int run = 0;
#pragma unroll
    for (int i = 0; i < 4; i++) {
        v[i] = (base + i < n) ? deg[base + i] : 0;
        run += v[i];
        p[i] = run;
    }
    int incl = run;
#pragma unroll
    for (int o = 1; o < 32; o <<= 1) {
        int x = __shfl_up_sync(0xffffffffu, incl, o);
        if (lane >= o) incl += x;
    }
    int wexcl = incl - run;
    if (lane == 31) wsum[w] = incl;
    __syncthreads();
    if (t == 0) {
        int a = 0;
#pragma unroll
        for (int i = 0; i < 8; i++) { int x = wsum[i]; wsum[i] = a; a += x; }
    }
    __syncthreads();
    int off = bsum[blockIdx.x] + wsum[w] + wexcl;
#pragma unroll
    for (int i = 0; i < 4; i++) {
        int idx = base + i;
        if (idx < n) {
            rowptr[idx + 1] = off + p[i];
            pos[idx]        = off + p[i] - v[i];
        }
    }
    if (blockIdx.x == 0 && t == 0) rowptr[0] = 0;
}

__global__ void scatter_kernel(const void* __restrict__ ei, int E, int n,
                               int* pos, int* colsrc) {
    int et = blockIdx.x * blockDim.x + threadIdx.x;
    int ET = E + n;
    if (et >= ET) return;
    int s, d;
    if (et < E) { s = loadIdx(ei, et); d = loadIdx(ei, (long long)E + et); }
    else        { s = d = et - E; }
    int p = atomicAdd(&pos[d], 1);
    colsrc[p] = s;
}

// ---------------------------------------------------------------------------
// tf32 tensor-core GEMM: C[M,128] = op(A)[M,128] @ W[128,128]
// 128x128 tile, BK=32, 8 warps (4x2), warp tile 32x64, m16n8k8 tf32 mma.
// ---------------------------------------------------------------------------
__device__ __forceinline__ unsigned f2tf(float x) {
    unsigned r;
    asm("cvt.rna.tf32.f32 %0, %1;" : "=r"(r) : "f"(x));
    return r;
}

__device__ __forceinline__ void mma_tf32(float* c, const unsigned* a,
                                         unsigned b0, unsigned b1) {
    asm volatile(
        "mma.sync.aligned.m16n8k8.row.col.f32.tf32.tf32.f32 "
        "{%0,%1,%2,%3}, {%4,%5,%6,%7}, {%8,%9}, {%0,%1,%2,%3};"
        : "+f"(c[0]), "+f"(c[1]), "+f"(c[2]), "+f"(c[3])
        : "r"(a[0]), "r"(a[1]), "r"(a[2]), "r"(a[3]), "r"(b0), "r"(b1));
}

template <bool RELU_BIAS>
__global__ void gemm128_tc(const float* __restrict__ A, const float* __restrict__ W,
                           const float* __restrict__ bias, float* __restrict__ C, int M)
{
    __shared__ unsigned As[128][36];   // [row][k], pad 4
    __shared__ unsigned Bs[32][136];   // [k][col], pad 8

    int t = threadIdx.x, lane = t & 31, wid = t >> 5;
    int wm = wid & 3, wn = wid >> 2;          // warp_m 0..3, warp_n 0..1
    int rowBase = blockIdx.x * 128;

    float acc[2][8][4];
#pragma unroll
    for (int mt = 0; mt < 2; mt++)
#pragma unroll
        for (int nt = 0; nt < 8; nt++)
#pragma unroll
            for (int i = 0; i < 4; i++) acc[mt][nt][i] = 0.f;

    for (int k0 = 0; k0 < 128; k0 += 32) {
        // A chunk: 128 rows x 32 k  (1024 float4, 4 per thread)
#pragma unroll
        for (int r = 0; r < 4; r++) {
            int id = t + r * 256;
            int arow = id >> 3;
            int cg   = (id & 7) * 4;
            int grow = rowBase + arow;
            float4 v = make_float4(0.f, 0.f, 0.f, 0.f);
            if (grow < M)
                v = *(const float4*)(A + (size_t)grow * 128 + k0 + cg);
            if (RELU_BIAS) {
                const float* bb = bias + k0 + cg;
                v.x = fmaxf(v.x + bb[0], 0.f);
                v.y = fmaxf(v.y + bb[1], 0.f);
                v.z = fmaxf(v.z + bb[2], 0.f);
                v.w = fmaxf(v.w + bb[3], 0.f);
            }
            As[arow][cg + 0] = f2tf(v.x);
            As[arow][cg + 1] = f2tf(v.y);
            As[arow][cg + 2] = f2tf(v.z);
            As[arow][cg + 3] = f2tf(v.w);
        }
        // W chunk: 32 k-rows x 128 cols
#pragma unroll
        for (int r = 0; r < 4; r++) {
            int id = t + r * 256;
            int krow = id >> 5;
            int c4   = (id & 31) * 4;
            float4 w = *(const float4*)(W + (size_t)(k0 + krow) * 128 + c4);
            Bs[krow][c4 + 0] = f2tf(w.x);
            Bs[krow][c4 + 1] = f2tf(w.y);
            Bs[krow][c4 + 2] = f2tf(w.z);
            Bs[krow][c4 + 3] = f2tf(w.w);
        }
        __syncthreads();

#pragma unroll
        for (int ks = 0; ks < 4; ks++) {
            int kk = ks * 8;
            unsigned a[2][4];
#pragma unroll
            for (int mt = 0; mt < 2; mt++) {
                int row = wm * 32 + mt * 16 + (lane >> 2);
                int kc  = kk + (lane & 3);
                a[mt][0] = As[row][kc];
                a[mt][1] = As[row + 8][kc];
                a[mt][2] = As[row][kc + 4];
                a[mt][3] = As[row + 8][kc + 4];
            }
#pragma unroll
            for (int nt = 0; nt < 8; nt++) {
                int col = wn * 64 + nt * 8 + (lane >> 2);
                int kc  = kk + (lane & 3);
                unsigned b0 = Bs[kc][col];
                unsigned b1 = Bs[kc + 4][col];
                mma_tf32(acc[0][nt], a[0], b0, b1);
                mma_tf32(acc[1][nt], a[1], b0, b1);
            }
        }
        __syncthreads();
    }

    // epilogue
#pragma unroll
    for (int mt = 0; mt < 2; mt++) {
#pragma unroll
        for (int nt = 0; nt < 8; nt++) {
            int row = rowBase + wm * 32 + mt * 16 + (lane >> 2);
            int col = wn * 64 + nt * 8 + (lane & 3) * 2;
            if (row < M)
                *(float2*)(C + (size_t)row * 128 + col) =
                    make_float2(acc[mt][nt][0], acc[mt][nt][1]);
            if (row + 8 < M)
                *(float2*)(C + (size_t)(row + 8) * 128 + col) =
                    make_float2(acc[mt][nt][2], acc[mt][nt][3]);
        }
    }
}

// ---------------------------------------------------------------------------
// alpha_src / alpha_dst
// ---------------------------------------------------------------------------
template <int H>
__global__ void alpha_kernel(const float* __restrict__ h,
                             const float* __restrict__ attS,
                             const float* __restrict__ attD,
                             float* __restrict__ aS, float* __restrict__ aD, int n)
{
    int w    = (int)((blockIdx.x * (size_t)blockDim.x + threadIdx.x) >> 5);
    int lane = threadIdx.x & 31;
    if (w >= n) return;
    float4 v = *(const float4*)(h + (size_t)w * 128 + lane * 4);
    float4 s = *(const float4*)(attS + lane * 4);
    float4 d = *(const float4*)(attD + lane * 4);
    float ps = v.x * s.x + v.y * s.y + v.z * s.z + v.w * s.w;
    float pd = v.x * d.x + v.y * d.y + v.z * d.z + v.w * d.w;
    const int LPH = 32 / H;
#pragma unroll
    for (int o = LPH >> 1; o; o >>= 1) {
        ps += __shfl_xor_sync(0xffffffffu, ps, o);
        pd += __shfl_xor_sync(0xffffffffu, pd, o);
    }
    if ((lane & (LPH - 1)) == 0) {
        int hd = lane / LPH;
        aS[(size_t)w * H + hd] = ps;
        aD[(size_t)w * H + hd] = pd;
    }
}

// ---------------------------------------------------------------------------
// warp-per-node online softmax + aggregation (no atomics)
// ---------------------------------------------------------------------------
template <int H, bool ADD_BIAS>
__global__ void node_agg_kernel(const int* __restrict__ rowptr,
                                const int* __restrict__ colsrc,
                                const float* __restrict__ aS,
                                const float* __restrict__ aD,
                                const float* __restrict__ hmat,
                                const float* __restrict__ bias,
                                float* __restrict__ out, int n)
{
    int d    = (int)((blockIdx.x * (size_t)blockDim.x + threadIdx.x) >> 5);
    int lane = threadIdx.x & 31;
    if (d >= n) return;
    int beg = rowptr[d], end = rowptr[d + 1];

    float aDd[H];
#pragma unroll
    for (int h = 0; h < H; h++) aDd[h] = aD[(size_t)d * H + h];

    float m[H], s[H];
#pragma unroll
    for (int h = 0; h < H; h++) { m[h] = NEG_BIG; s[h] = 0.f; }
    for (int i = beg + lane; i < end; i += 32) {
        int sidx = colsrc[i];
#pragma unroll
        for (int h = 0; h < H; h++) {
            float e = aS[(size_t)sidx * H + h] + aDd[h];
            e = e > 0.f ? e : 0.2f * e;
            float mn = fmaxf(m[h], e);
            s[h] = s[h] * __expf(m[h] - mn) + __expf(e - mn);
            m[h] = mn;
        }
    }
#pragma unroll
    for (int o = 16; o; o >>= 1) {
#pragma unroll
        for (int h = 0; h < H; h++) {
            float mo = __shfl_xor_sync(0xffffffffu, m[h], o);
            float so = __shfl_xor_sync(0xffffffffu, s[h], o);
            float mn = fmaxf(m[h], mo);
            s[h] = s[h] * __expf(m[h] - mn) + so * __expf(mo - mn);
            m[h] = mn;
        }
    }

    const int OC = 128 / H;
    int hd = (lane * 4) / OC;
    float mxh = m[hd];
    float aDh = aDd[hd];
    float inv = 1.f / fmaxf(s[hd], 1e-16f);
    float4 acc = make_float4(0.f, 0.f, 0.f, 0.f);
    for (int base = beg; base < end; base += 32) {
        int cnt = min(32, end - base);
        int idx = base + lane;
        int sv  = (idx < end) ? colsrc[idx] : 0;
#pragma unroll 4
        for (int j = 0; j < cnt; j++) {
            int sidx = __shfl_sync(0xffffffffu, sv, j);
            float e = aS[(size_t)sidx * H + hd] + aDh;
            e = e > 0.f ? e : 0.2f * e;
            float wgt = __expf(e - mxh) * inv;
            float4 v = *(const float4*)(hmat + (size_t)sidx * 128 + lane * 4);
            acc.x += wgt * v.x;
            acc.y += wgt * v.y;
            acc.z += wgt * v.z;
            acc.w += wgt * v.w;
        }
    }
    if (ADD_BIAS) {
        float4 b = *(const float4*)(bias + lane * 4);
        acc.x += b.x; acc.y += b.y; acc.z += b.z; acc.w += b.w;
    }
    *(float4*)(out + (size_t)d * 128 + lane * 4) = acc;
}

// ---------------------------------------------------------------------------
// host
// ---------------------------------------------------------------------------
extern "C" void kernel_launch(void* const* d_in, const int* in_sizes, int n_in,
                              void* d_out, int out_size)
{
    const float* x   = (const float*)d_in[0];
    const void*  ei  = d_in[1];
    const float* W1  = (const float*)d_in[2];
    const float* as1 = (const float*)d_in[3];
    const float* ad1 = (const float*)d_in[4];
    const float* b1  = (const float*)d_in[5];
    const float* W2  = (const float*)d_in[6];
    const float* as2 = (const float*)d_in[7];
    const float* ad2 = (const float*)d_in[8];
    const float* b2  = (const float*)d_in[9];
    float* out = (float*)d_out;

    int n  = in_sizes[0] / 128;
    int E  = in_sizes[1] / 2;
    int ET = E + n;

    float *h, *agg, *aS, *aD;
    int *deg, *rowptr, *pos, *colsrc, *bsum;
    cudaGetSymbolAddress((void**)&h,      g_h);
    cudaGetSymbolAddress((void**)&agg,    g_agg);
    cudaGetSymbolAddress((void**)&aS,     g_aS);
    cudaGetSymbolAddress((void**)&aD,     g_aD);
    cudaGetSymbolAddress((void**)&deg,    g_deg);
    cudaGetSymbolAddress((void**)&rowptr, g_rowptr);
    cudaGetSymbolAddress((void**)&pos,    g_pos);
    cudaGetSymbolAddress((void**)&colsrc, g_colsrc);
    cudaGetSymbolAddress((void**)&bsum,   g_bsum);

    const int TB = 256;
    int gridGemm  = (n + 127) / 128;
    int gridEdge  = (ET + TB - 1) / TB;
    int gridNodeW = (n + 7) / 8;
    int nScanBlk  = (n + 1023) / 1024;

    // ----- CSR build (once) -----
    detect_kernel<<<1, 1>>>((const int*)ei);
    zero_int<<<(n + TB - 1) / TB, TB>>>(deg, n);
    hist_kernel<<<gridEdge, TB>>>(ei, E, n, deg);
    block_sum_kernel<<<nScanBlk, 256>>>(deg, bsum, n);
    scan_bsum_kernel<<<1, 1>>>(bsum, nScanBlk);
    scan_final_kernel<<<nScanBlk, 256>>>(deg, bsum, rowptr, pos, n);
    scatter_kernel<<<gridEdge, TB>>>(ei, E, n, pos, colsrc);

    // ----- layer 1 (H=4) -----
    gemm128_tc<false><<<gridGemm, TB>>>(x, W1, nullptr, h, n);
    alpha_kernel<4><<<gridNodeW, TB>>>(h, as1, ad1, aS, aD, n);
    node_agg_kernel<4, false><<<gridNodeW, TB>>>(rowptr, colsrc, aS, aD, h,
                                                 nullptr, agg, n);

    // ----- layer 2 (H=1) -----
    gemm128_tc<true><<<gridGemm, TB>>>(agg, W2, b1, h, n);
    alpha_kernel<1><<<gridNodeW, TB>>>(h, as2, ad2, aS, aD, n);
    node_agg_kernel<1, true><<<gridNodeW, TB>>>(rowptr, colsrc, aS, aD, h,
                                                b2, out, n);
}